// round 5
// baseline (speedup 1.0000x reference)
#include <cuda_runtime.h>
#include <math.h>
#include <stdint.h>

#define TT 512
#define BB 64
#define HH 512
#define NI 512
#define GRID 128
#define NTHREADS 256
#define AST 68   // staging row stride in floats (16B-aligned rows, bank-skewed)

// ---------------- device globals (no allocation allowed) ----------------
__device__ unsigned long long g_arrive;
__device__ unsigned long long g_release;
__device__ float g_s[5][BB * HH];   // scratch for states s0..s4 (full rows)

struct __align__(16) SmemLayout {
    float buf[2][BB * AST];   // activation staging, double buffered (34,816 B)
    float wT0[8 * 1024];      // W0 slice transposed [col][k]        (32,768 B)
    float wTs[8][8 * 512];    // Ws[i] slices transposed [i][col][k] (131,072 B)
    float red[8 * 512];       // per-warp partials [warp][row*8+col] (16,384 B)
    float ch[512];            // reduced pre-activations [row*8+col] (2,048 B)
    float sl[9][BB * 4];      // local state slices [state][b*4+pj]  (9,216 B)
};  // total 226,304 B  (< 227 KB opt-in)

__device__ __forceinline__ void fma2(unsigned long long &d, unsigned long long a,
                                     unsigned long long b) {
    asm("fma.rn.f32x2 %0, %1, %2, %0;" : "+l"(d) : "l"(a), "l"(b));
}

// Monotonic grid barrier: safe across graph replays (counters never reset).
// All 128 CTAs are co-resident (1 CTA/SM via 226KB smem), so spinning is safe.
__device__ __forceinline__ void grid_bar(int tid) {
    __syncthreads();
    if (tid == 0) {
        __threadfence();
        unsigned long long a = atomicAdd(&g_arrive, 1ULL) + 1ULL;
        unsigned long long phase = (a + (GRID - 1)) / GRID;
        if (a == phase * (unsigned long long)GRID) {
            asm volatile("st.release.gpu.u64 [%0], %1;"
                         :: "l"(&g_release), "l"(phase) : "memory");
        } else {
            unsigned long long v;
            do {
                asm volatile("ld.acquire.gpu.u64 %0, [%1];"
                             : "=l"(v) : "l"(&g_release) : "memory");
            } while (v < phase);
        }
        __threadfence();
    }
    __syncthreads();
}

// Stage one [64 rows x 64 k] fp32 chunk into smem (cp.async.cg: L2 path, coherent).
__device__ __forceinline__ void stage_chunk(float* dst, const float* src0,
                                            const float* src1, int k0, int tid) {
    const float* src = (k0 < 512) ? (src0 + k0) : (src1 + (k0 - 512));
#pragma unroll
    for (int q = 0; q < 4; ++q) {
        int f = tid + q * NTHREADS;           // 0..1023 float4s
        int row = f >> 4;
        int kq = (f & 15) << 2;
        const float* g = src + row * 512 + kq;
        float* d = dst + row * AST + kq;
        unsigned int da = (unsigned int)__cvta_generic_to_shared(d);
        asm volatile("cp.async.cg.shared.global [%0], [%1], 16;" :: "r"(da), "l"(g));
    }
}

// One DAG level: C[64,8] = A[64,K] @ Wslice for NSETS weight sets sharing A,
// then reduce + sigmoid/act/gating, store local slice (+ optional global).
template <int NSETS, int K>
__device__ __forceinline__ void do_level(SmemLayout* sm, int tid,
        const float* __restrict__ src0, const float* __restrict__ src1,
        const float* w0s, const float* w1s,
        int act0, int act1, int pred0, int pred1, int st0, int st1,
        float* gd0, float* gd1,
        const float* __restrict__ hprevRow, int colbase) {
    const int warp = tid >> 5, lane = tid & 31;
    const int ri = lane & 15, ci = lane >> 4;

    unsigned long long acc[NSETS][4][4];
#pragma unroll
    for (int s = 0; s < NSETS; ++s)
#pragma unroll
        for (int i = 0; i < 4; ++i)
#pragma unroll
            for (int j = 0; j < 4; ++j) acc[s][i][j] = 0ULL;

    constexpr int NCH = K / 64;
    stage_chunk(sm->buf[0], src0, src1, 0, tid);
    asm volatile("cp.async.commit_group;");
    for (int c = 0; c < NCH; ++c) {
        if (c + 1 < NCH) {
            stage_chunk(sm->buf[(c + 1) & 1], src0, src1, (c + 1) * 64, tid);
            asm volatile("cp.async.commit_group;");
            asm volatile("cp.async.wait_group 1;");
        } else {
            asm volatile("cp.async.wait_group 0;");
        }
        __syncthreads();
        const float* bp = sm->buf[c & 1];
        const int kw = c * 64 + warp * 8;   // this warp's k-slice (global k)
#pragma unroll
        for (int t4 = 0; t4 < 8; t4 += 4) {
            ulonglong2 a2[4];
#pragma unroll
            for (int i = 0; i < 4; ++i)
                a2[i] = *reinterpret_cast<const ulonglong2*>(
                    bp + (ri + 16 * i) * AST + warp * 8 + t4);
#pragma unroll
            for (int s = 0; s < NSETS; ++s) {
                const float* wb = (s == 0) ? w0s : w1s;
#pragma unroll
                for (int j = 0; j < 4; ++j) {
                    ulonglong2 w2 = *reinterpret_cast<const ulonglong2*>(
                        wb + (4 * ci + j) * K + kw + t4);
#pragma unroll
                    for (int i = 0; i < 4; ++i) {
                        fma2(acc[s][i][j], a2[i].x, w2.x);
                        fma2(acc[s][i][j], a2[i].y, w2.y);
                    }
                }
            }
        }
        __syncthreads();
    }

    const int b = tid >> 2, pj = tid & 3;
#pragma unroll
    for (int s = 0; s < NSETS; ++s) {
#pragma unroll
        for (int i = 0; i < 4; ++i)
#pragma unroll
            for (int j = 0; j < 4; ++j) {
                float2 f = *reinterpret_cast<float2*>(&acc[s][i][j]);
                sm->red[warp * 512 + (ri + 16 * i) * 8 + (4 * ci + j)] = f.x + f.y;
            }
        __syncthreads();
        for (int o = tid; o < 512; o += NTHREADS) {
            float v = 0.f;
#pragma unroll
            for (int w = 0; w < 8; ++w) v += sm->red[w * 512 + o];
            sm->ch[o] = v;
        }
        __syncthreads();
        {
            int act = (s == 0) ? act0 : act1;
            int pred = (s == 0) ? pred0 : pred1;
            int st = (s == 0) ? st0 : st1;
            float* gd = (s == 0) ? gd0 : gd1;
            float gv = sm->ch[b * 8 + pj];
            float cv = sm->ch[b * 8 + 4 + pj];
            float gate = 1.f / (1.f + expf(-gv));
            float hh;
            if (act == 0)      hh = tanhf(cv);
            else if (act == 1) hh = fmaxf(cv, 0.f);
            else if (act == 2) hh = 1.f / (1.f + expf(-cv));
            else               hh = cv;
            float sp = (pred < 0) ? hprevRow[b * 512 + colbase + pj]
                                  : sm->sl[pred][b * 4 + pj];
            float sv = fmaf(gate, hh - sp, sp);
            sm->sl[st][b * 4 + pj] = sv;
            if (gd) gd[b * 512 + colbase + pj] = sv;
        }
        __syncthreads();
    }
}

__global__ void __launch_bounds__(NTHREADS, 1)
nao_kernel(const float* __restrict__ x, const float* __restrict__ h0,
           const float* __restrict__ W0, const float* __restrict__ Ws,
           float* __restrict__ out, long long out_size) {
    extern __shared__ unsigned char smemRaw[];
    SmemLayout* sm = reinterpret_cast<SmemLayout*>(smemRaw);
    const int tid = threadIdx.x;
    const int colbase = blockIdx.x * 4;

    // One-time: load this CTA's transposed weight slices (amortized over T=512).
    for (int idx = tid; idx < 8 * 1024; idx += NTHREADS) {
        int j = idx >> 10, k = idx & 1023;
        int gc = (j < 4) ? (colbase + j) : (512 + colbase + j - 4);
        sm->wT0[j * 1024 + k] = W0[k * 1024 + gc];
    }
    for (int i = 0; i < 8; ++i)
        for (int idx = tid; idx < 8 * 512; idx += NTHREADS) {
            int j = idx >> 9, k = idx & 511;
            int gc = (j < 4) ? (colbase + j) : (512 + colbase + j - 4);
            sm->wTs[i][j * 512 + k] =
                Ws[(size_t)i * 512 * 1024 + (size_t)k * 1024 + gc];
        }
    __syncthreads();

    for (int t = 0; t < TT; ++t) {
        const float* xt = x + (size_t)t * BB * NI;
        const float* hRow = (t == 0) ? h0 : (out + (size_t)(t - 1) * BB * HH);

        // Level 0: s0 = h + sigm(gate)*(tanh(cand) - h), from [x;h] @ W0
        do_level<1, 1024>(sm, tid, xt, hRow, sm->wT0, nullptr,
                          0, 0, -1, 0, 0, 0, g_s[0], nullptr, hRow, colbase);
        grid_bar(tid);
        // Level 1: s1 (tanh), s2 (relu), both from s0
        do_level<2, 512>(sm, tid, g_s[0], g_s[0], sm->wTs[0], sm->wTs[1],
                         0, 1, 0, 0, 1, 2, g_s[1], g_s[2], nullptr, colbase);
        grid_bar(tid);
        // Level 2: s3 (sigm), s4 (id) from s1; s5 (tanh), s6 (relu) from s2
        do_level<2, 512>(sm, tid, g_s[1], g_s[1], sm->wTs[2], sm->wTs[3],
                         2, 3, 1, 1, 3, 4, g_s[3], g_s[4], nullptr, colbase);
        do_level<2, 512>(sm, tid, g_s[2], g_s[2], sm->wTs[4], sm->wTs[5],
                         0, 1, 2, 2, 5, 6, nullptr, nullptr, nullptr, colbase);
        grid_bar(tid);
        // Level 3: s7 (sigm) from s3; s8 (id) from s4
        do_level<1, 512>(sm, tid, g_s[3], g_s[3], sm->wTs[6], nullptr,
                         2, 0, 3, 0, 7, 0, nullptr, nullptr, nullptr, colbase);
        do_level<1, 512>(sm, tid, g_s[4], g_s[4], sm->wTs[7], nullptr,
                         3, 0, 4, 0, 8, 0, nullptr, nullptr, nullptr, colbase);
        // h_new = mean(s1..s8); write into out (also the h-history buffer)
        {
            const int b = tid >> 2, pj = tid & 3;
            float m = 0.f;
#pragma unroll
            for (int s2 = 1; s2 <= 8; ++s2) m += sm->sl[s2][b * 4 + pj];
            m *= 0.125f;
            out[(size_t)t * BB * HH + b * 512 + colbase + pj] = m;
            if (t == TT - 1 &&
                out_size >= (long long)TT * BB * HH + (long long)BB * HH)
                out[(size_t)TT * BB * HH + b * 512 + colbase + pj] = m;
        }
        grid_bar(tid);
    }
}

extern "C" void kernel_launch(void* const* d_in, const int* in_sizes, int n_in,
                              void* d_out, int out_size) {
    const float* x  = (const float*)d_in[0];
    const float* h0 = (const float*)d_in[1];
    const float* W0 = (const float*)d_in[2];
    const float* Ws = (const float*)d_in[3];
    float* out = (float*)d_out;
    cudaFuncSetAttribute(nao_kernel, cudaFuncAttributeMaxDynamicSharedMemorySize,
                         (int)sizeof(SmemLayout));
    nao_kernel<<<GRID, NTHREADS, sizeof(SmemLayout)>>>(x, h0, W0, Ws, out,
                                                       (long long)out_size);
}